// round 15
// baseline (speedup 1.0000x reference)
#include <cuda_runtime.h>
#include <cuda_fp16.h>
#include <cstdint>

#define N_NODES 100000
#define N_EDGES 1600000
#define NCHUNK 196       // 196*512 >= N_NODES (scan chunks of 512)
#define NBG 592          // 4 blocks/SM x 148 SMs -> co-resident, barrier-safe
#define NTG 256

// ---------------- scratch (device globals; no allocation allowed) ----------
__device__ __half g_yh[N_NODES * 32];   // x @ W1_l  (fp16, gather source)
__device__ float  g_z[N_NODES * 32];    // x @ W1_r  (fp32)
__device__ __half g_h1h[N_NODES * 32];  // h1 fp16 (gather source, layer 2)
__device__ float  g_h1f[N_NODES * 32];  // h1 fp32 (dense self term)
__device__ float  g_m2[N_NODES * 32];   // layer-2 gathered mean
__device__ int2   g_edge[N_EDGES];      // packed (src, dst)
__device__ int    g_csr[N_EDGES];       // src ids grouped by dst
__device__ int    g_off[N_NODES + 1];   // counts -> exclusive offsets
__device__ int    g_part[N_NODES + 512];// scan partials
__device__ int    g_cur[N_NODES];       // bucket cursors
__device__ int    g_bsum[256];
__device__ int    g_is64;
__device__ unsigned g_arrive;
__device__ unsigned g_release;

// ---------------- JAX threefry2x32 (partitionable scheme) ------------------
struct TF2 { uint32_t a, b; };

__host__ __device__ constexpr uint32_t rotl32(uint32_t v, int r) {
    return (v << r) | (v >> (32 - r));
}

__host__ __device__ constexpr TF2 threefry(uint32_t k0, uint32_t k1,
                                           uint32_t x0, uint32_t x1) {
    const uint32_t ks0 = k0, ks1 = k1, ks2 = k0 ^ k1 ^ 0x1BD11BDAu;
    const int ra[4] = {13, 15, 26, 6};
    const int rb[4] = {17, 29, 16, 24};
    x0 += ks0; x1 += ks1;
#pragma unroll
    for (int i = 0; i < 4; i++) { x0 += x1; x1 = rotl32(x1, ra[i]); x1 ^= x0; }
    x0 += ks1; x1 += ks2 + 1u;
#pragma unroll
    for (int i = 0; i < 4; i++) { x0 += x1; x1 = rotl32(x1, rb[i]); x1 ^= x0; }
    x0 += ks2; x1 += ks0 + 2u;
#pragma unroll
    for (int i = 0; i < 4; i++) { x0 += x1; x1 = rotl32(x1, ra[i]); x1 ^= x0; }
    x0 += ks0; x1 += ks1 + 3u;
#pragma unroll
    for (int i = 0; i < 4; i++) { x0 += x1; x1 = rotl32(x1, rb[i]); x1 ^= x0; }
    x0 += ks1; x1 += ks2 + 4u;
#pragma unroll
    for (int i = 0; i < 4; i++) { x0 += x1; x1 = rotl32(x1, ra[i]); x1 ^= x0; }
    x0 += ks2; x1 += ks0 + 5u;
    return {x0, x1};
}

constexpr TF2 DK0 = threefry(0u, 42u, 0u, 0u);
constexpr TF2 DK1 = threefry(0u, 42u, 0u, 1u);

template <uint32_t K0, uint32_t K1>
__device__ __forceinline__ bool drop_bit(uint32_t j) {
    TF2 r = threefry(K0, K1, 0u, j);
    return ((r.a ^ r.b) >> 31) != 0;   // MSB set -> u >= 0.5 -> dropped
}

// ---------------- packed f32x2 helpers (sm_103a) ---------------------------
typedef unsigned long long ULL;
__device__ __forceinline__ ULL pk2(float x, float y) {
    ULL r;
    asm("mov.b64 %0, {%1, %2};" : "=l"(r) : "f"(x), "f"(y));
    return r;
}
__device__ __forceinline__ ULL fma2(ULL a, ULL b, ULL c) {
    ULL d;
    asm("fma.rn.f32x2 %0, %1, %2, %3;" : "=l"(d) : "l"(a), "l"(b), "l"(c));
    return d;
}
__device__ __forceinline__ void upk2(ULL v, float& x, float& y) {
    asm("mov.b64 {%0, %1}, %2;" : "=f"(x), "=f"(y) : "l"(v));
}

// ---------------- k_pre: dense pre-GEMM + resets + dtype detect -------------
__global__ void __launch_bounds__(256) k_pre(const float* __restrict__ x,
                      const float* __restrict__ Wl,
                      const float* __restrict__ Wr,
                      const uint32_t* __restrict__ ei) {
    __shared__ float2 swlr[64 * 32];      // (Wl, Wr) pairs, 16KB
    __shared__ float  rows[8][4][64];     // 8KB
    int tid = threadIdx.x;
    for (int i = tid; i < 2048; i += 256) swlr[i] = make_float2(Wl[i], Wr[i]);
    int gt = blockIdx.x * 256 + tid;
    if (gt <= N_NODES) g_off[gt] = 0;
    if (blockIdx.x == 0 && tid == 0) {
        g_arrive = 0u;
        g_release = 0u;
        int is64 = 1;
        for (int k = 0; k < 64; k++)
            if (ei[2 * k + 1] != 0u) { is64 = 0; break; }
        g_is64 = is64;
    }
    int w = tid >> 5, lane = tid & 31;
    int nb = blockIdx.x * 32 + w * 4;     // grid = 3125 exact
#pragma unroll
    for (int n = 0; n < 4; n++) {
        rows[w][n][lane]      = x[(nb + n) * 64 + lane];
        rows[w][n][32 + lane] = x[(nb + n) * 64 + 32 + lane];
    }
    __syncthreads();
    ULL acc[4];
#pragma unroll
    for (int n = 0; n < 4; n++) acc[n] = pk2(0.f, 0.f);
#pragma unroll
    for (int k = 0; k < 64; k++) {
        float2 wv = swlr[k * 32 + lane];
        ULL wp = pk2(wv.x, wv.y);
#pragma unroll
        for (int n = 0; n < 4; n++) {
            float xv = rows[w][n][k];
            acc[n] = fma2(pk2(xv, xv), wp, acc[n]);
        }
    }
#pragma unroll
    for (int n = 0; n < 4; n++) {
        float yl, yr;
        upk2(acc[n], yl, yr);
        g_yh[(nb + n) * 32 + lane] = __float2half_rn(yl);
        g_z[(nb + n) * 32 + lane]  = yr;
    }
}

// ---------------- k_graph: full CSR build in ONE launch ----------------------
__global__ void __launch_bounds__(NTG, 4) k_graph(const uint32_t* __restrict__ ei) {
    __shared__ int sh[NTG];
    const int tid = threadIdx.x;
    const int bid = blockIdx.x;
    unsigned target = 0;

    auto GBAR = [&]() {
        __syncthreads();
        __threadfence();
        target += 1;
        if (tid == 0) {
            unsigned a = atomicAdd(&g_arrive, 1u) + 1u;
            if (a == target * NBG) {
                *((volatile unsigned*)&g_release) = target;
            } else {
                while (*((volatile unsigned*)&g_release) < target) __nanosleep(64);
            }
        }
        __syncthreads();
    };

    // ---- phase 1: pack edges + dst histogram ----
    {
        int is64 = g_is64;
        for (int e = bid * NTG + tid; e < N_EDGES; e += NBG * NTG) {
            int s, d;
            if (is64) {
                uint2 sv = reinterpret_cast<const uint2*>(ei)[e];
                uint2 dv = reinterpret_cast<const uint2*>(ei)[N_EDGES + e];
                s = (int)sv.x; d = (int)dv.x;
            } else {
                s = (int)ei[e];
                d = (int)ei[N_EDGES + e];
            }
            g_edge[e] = make_int2(s, d);
            atomicAdd(&g_off[d], 1);
        }
    }
    GBAR();   // 1

    // ---- phase 2: per-chunk exclusive scan (512 counts/chunk, 2/thread) ----
    if (bid < NCHUNK) {
        int i0 = bid * 512 + tid * 2;
        int v0 = (i0     < N_NODES) ? __ldcg(&g_off[i0])     : 0;
        int v1 = (i0 + 1 < N_NODES) ? __ldcg(&g_off[i0 + 1]) : 0;
        int s2 = v0 + v1;
        sh[tid] = s2;
        __syncthreads();
        for (int o = 1; o < NTG; o <<= 1) {
            int t = (tid >= o) ? sh[tid - o] : 0;
            __syncthreads();
            sh[tid] += t;
            __syncthreads();
        }
        int ex = sh[tid] - s2;
        if (i0     < N_NODES) g_part[i0]     = ex;
        if (i0 + 1 < N_NODES) g_part[i0 + 1] = ex + v0;
        if (tid == NTG - 1) g_bsum[bid] = sh[NTG - 1];
    }
    GBAR();   // 2

    // ---- phase 3: apply (reduce preceding chunk totals, write offs+cursors) --
    if (bid < NCHUNK) {
        int v = (tid < bid) ? __ldcg(&g_bsum[tid]) : 0;   // bid <= 195 < 256
        sh[tid] = v;
        __syncthreads();
        for (int o = NTG / 2; o > 0; o >>= 1) {
            if (tid < o) sh[tid] += sh[tid + o];
            __syncthreads();
        }
        int base = sh[0];
        for (int idx = tid; idx < 512; idx += NTG) {
            int i = bid * 512 + idx;
            if (i < N_NODES) {
                int o = g_part[i] + base;
                g_off[i] = o;
                g_cur[i] = o;
            }
        }
        if (bid == 0 && tid == 0) g_off[N_NODES] = N_EDGES;
    }
    GBAR();   // 3

    // ---- phase 4: bucket scatter (CSR fill) ----
    for (int e = bid * NTG + tid; e < N_EDGES; e += NBG * NTG) {
        int2 p = g_edge[e];
        int pos = atomicAdd(&g_cur[p.y], 1);
        g_csr[pos] = p.x;
    }
}

// ---------------- fp16 gather: 2 row-groups, 8 loads/lane in flight ----------
// lane = r*16 + c. Main loop covers 16 rows/iter (8 per r-group).
__device__ __forceinline__ float2 gather_h2(const __half2* __restrict__ buf,
                                            int beg, int end, int lane) {
    int r = lane >> 4;       // row-group 0/1
    int c = lane & 15;       // half2 column
    float acx = 0.f, acy = 0.f;
    int j = beg;
    for (; j + 16 <= end; j += 16) {
        int i0 = __ldg(g_csr + j + r);
        int i1 = __ldg(g_csr + j + 2 + r);
        int i2 = __ldg(g_csr + j + 4 + r);
        int i3 = __ldg(g_csr + j + 6 + r);
        int i4 = __ldg(g_csr + j + 8 + r);
        int i5 = __ldg(g_csr + j + 10 + r);
        int i6 = __ldg(g_csr + j + 12 + r);
        int i7 = __ldg(g_csr + j + 14 + r);
        float2 a0 = __half22float2(__ldg(buf + i0 * 16 + c));
        float2 a1 = __half22float2(__ldg(buf + i1 * 16 + c));
        float2 a2 = __half22float2(__ldg(buf + i2 * 16 + c));
        float2 a3 = __half22float2(__ldg(buf + i3 * 16 + c));
        float2 a4 = __half22float2(__ldg(buf + i4 * 16 + c));
        float2 a5 = __half22float2(__ldg(buf + i5 * 16 + c));
        float2 a6 = __half22float2(__ldg(buf + i6 * 16 + c));
        float2 a7 = __half22float2(__ldg(buf + i7 * 16 + c));
        acx += ((a0.x + a1.x) + (a2.x + a3.x)) + ((a4.x + a5.x) + (a6.x + a7.x));
        acy += ((a0.y + a1.y) + (a2.y + a3.y)) + ((a4.y + a5.y) + (a6.y + a7.y));
    }
    for (; j + 4 <= end; j += 4) {
        int i0 = __ldg(g_csr + j + r);
        int i1 = __ldg(g_csr + j + 2 + r);
        float2 a = __half22float2(__ldg(buf + i0 * 16 + c));
        float2 b = __half22float2(__ldg(buf + i1 * 16 + c));
        acx += a.x + b.x;
        acy += a.y + b.y;
    }
    if (j + 2 <= end) {
        int i0 = __ldg(g_csr + j + r);
        float2 a = __half22float2(__ldg(buf + i0 * 16 + c));
        acx += a.x; acy += a.y;
        j += 2;
    }
    if (j < end && r == 0) {     // odd remainder handled by row-group 0 only
        int i0 = __ldg(g_csr + j);
        float2 a = __half22float2(__ldg(buf + i0 * 16 + c));
        acx += a.x; acy += a.y;
    }
    acx += __shfl_xor_sync(0xffffffffu, acx, 16);
    acy += __shfl_xor_sync(0xffffffffu, acy, 16);
    return make_float2(acx, acy);
}

// layer 1: warp per node; fp16 gather-mean + bias + z + lrelu + dropout
__global__ void k_agg1(const float* __restrict__ b) {
    int w = threadIdx.x >> 5, lane = threadIdx.x & 31;
    int node = blockIdx.x * 8 + w;                    // grid = 12500 exact
    int beg = g_off[node], end = g_off[node + 1];
    float2 acc = gather_h2(reinterpret_cast<const __half2*>(g_yh), beg, end, lane);
    if (lane < 16) {
        int c2 = 2 * lane;
        float inv = 1.0f / fmaxf((float)(end - beg), 1.0f);
        float2 z2 = *reinterpret_cast<const float2*>(g_z + node * 32 + c2);
        float2 bb = *reinterpret_cast<const float2*>(b + c2);
        float v0 = fmaf(acc.x, inv, bb.x + z2.x);
        float v1 = fmaf(acc.y, inv, bb.y + z2.y);
        v0 = v0 > 0.f ? v0 : 0.01f * v0;
        v1 = v1 > 0.f ? v1 : 0.01f * v1;
        uint32_t jj = (uint32_t)(node * 32 + c2);
        v0 = drop_bit<DK0.a, DK0.b>(jj)      ? 0.f : 2.0f * v0;
        v1 = drop_bit<DK0.a, DK0.b>(jj + 1u) ? 0.f : 2.0f * v1;
        *reinterpret_cast<float2*>(g_h1f + node * 32 + c2) = make_float2(v0, v1);
        reinterpret_cast<__half2*>(g_h1h)[node * 16 + lane] =
            __floats2half2_rn(v0, v1);
    }
}

// layer 2 gather: warp per node; fp16 gather-mean of h1 -> g_m2 (fp32)
__global__ void k_gather2() {
    int w = threadIdx.x >> 5, lane = threadIdx.x & 31;
    int node = blockIdx.x * 8 + w;                    // grid = 12500 exact
    int beg = g_off[node], end = g_off[node + 1];
    float2 acc = gather_h2(reinterpret_cast<const __half2*>(g_h1h), beg, end, lane);
    if (lane < 16) {
        float inv = 1.0f / fmaxf((float)(end - beg), 1.0f);
        *reinterpret_cast<float2*>(g_m2 + node * 32 + 2 * lane) =
            make_float2(acc.x * inv, acc.y * inv);
    }
}

// layer 2 dense: GEMMs (4 nodes/warp, packed weights) + dropout + l2norm
__global__ void __launch_bounds__(256) k_gemm2(const float* __restrict__ Wl,
                       const float* __restrict__ b,
                       const float* __restrict__ Wr,
                       float* __restrict__ out) {
    __shared__ float2 swl2[32 * 32], swr2[32 * 32];   // 8KB + 8KB
    __shared__ float  rows[8][4][64];                 // 8KB
    int tid = threadIdx.x;
    for (int i = tid; i < 1024; i += 256) {
        int k = i >> 5, c = i & 31;
        swl2[i] = make_float2(Wl[k * 64 + c], Wl[k * 64 + 32 + c]);
        swr2[i] = make_float2(Wr[k * 64 + c], Wr[k * 64 + 32 + c]);
    }
    __syncthreads();
    int w = tid >> 5, lane = tid & 31;
    int nb = blockIdx.x * 32 + w * 4;                 // grid = 3125 exact
#pragma unroll
    for (int n = 0; n < 4; n++) {
        int node = nb + n;
        rows[w][n][lane]      = g_m2[node * 32 + lane];
        rows[w][n][32 + lane] = g_h1f[node * 32 + lane];
    }
    __syncwarp();
    float bb0 = b[lane], bb1 = b[32 + lane];
    float a0[4], a1[4];
#pragma unroll
    for (int n = 0; n < 4; n++) { a0[n] = bb0; a1[n] = bb1; }
#pragma unroll
    for (int k = 0; k < 32; k++) {
        float2 wl = swl2[k * 32 + lane];
        float2 wr = swr2[k * 32 + lane];
#pragma unroll
        for (int n = 0; n < 4; n++) {
            float m = rows[w][n][k];
            float h = rows[w][n][32 + k];
            a0[n] = fmaf(m, wl.x, fmaf(h, wr.x, a0[n]));
            a1[n] = fmaf(m, wl.y, fmaf(h, wr.y, a1[n]));
        }
    }
#pragma unroll
    for (int n = 0; n < 4; n++) {
        int node = nb + n;
        uint32_t j0 = (uint32_t)(node * 64 + lane);
        float v0 = drop_bit<DK1.a, DK1.b>(j0)       ? 0.f : 2.0f * a0[n];
        float v1 = drop_bit<DK1.a, DK1.b>(j0 + 32u) ? 0.f : 2.0f * a1[n];
        float ss = v0 * v0 + v1 * v1;
#pragma unroll
        for (int o = 16; o > 0; o >>= 1)
            ss += __shfl_xor_sync(0xffffffffu, ss, o);
        float scale = 1.0f / fmaxf(sqrtf(ss), 1e-12f);
        out[node * 64 + lane]      = v0 * scale;
        out[node * 64 + 32 + lane] = v1 * scale;
    }
}

// ---------------- launch -----------------------------------------------------
extern "C" void kernel_launch(void* const* d_in, const int* in_sizes, int n_in,
                              void* d_out, int out_size) {
    const float*    x   = (const float*)d_in[0];
    const uint32_t* ei  = (const uint32_t*)d_in[1];   // int32 or int64 (detected)
    const float*    W1l = (const float*)d_in[2];
    const float*    b1  = (const float*)d_in[3];
    const float*    W1r = (const float*)d_in[4];
    const float*    W2l = (const float*)d_in[5];
    const float*    b2  = (const float*)d_in[6];
    const float*    W2r = (const float*)d_in[7];
    float* out = (float*)d_out;

    k_pre<<<N_NODES / 32, 256>>>(x, W1l, W1r, ei);     // 1
    k_graph<<<NBG, NTG>>>(ei);                         // 2 (CSR in one launch)
    k_agg1<<<N_NODES / 8, 256>>>(b1);                  // 3
    k_gather2<<<N_NODES / 8, 256>>>();                 // 4  <- ncu slot
    k_gemm2<<<N_NODES / 32, 256>>>(W2l, b2, W2r, out); // 5
}

// round 16
// speedup vs baseline: 1.0898x; 1.0898x over previous
#include <cuda_runtime.h>
#include <cuda_fp16.h>
#include <cstdint>

#define N_NODES 100000
#define N_EDGES 1600000
#define SCAN_BLK 512
#define NSCAN_BLKS 196   // 196*512 >= N_NODES

// ---------------- scratch (device globals; no allocation allowed) ----------
__device__ __half g_yh[N_NODES * 32];   // x @ W1_l  (fp16, gather source)
__device__ float  g_z[N_NODES * 32];    // x @ W1_r  (fp32)
__device__ __half g_h1h[N_NODES * 32];  // h1 fp16 (gather source, layer 2)
__device__ float  g_h1f[N_NODES * 32];  // h1 fp32 (dense self term)
__device__ float  g_m2[N_NODES * 32];   // layer-2 gathered mean
__device__ int2   g_edge[N_EDGES];      // packed (src, dst)
__device__ int    g_csr[N_EDGES];       // src ids grouped by dst
__device__ int    g_off[N_NODES + 1];   // counts -> exclusive offsets
__device__ int    g_part[N_NODES];      // scan partials
__device__ int    g_cur[N_NODES];       // bucket cursors
__device__ int    g_bsum[256];
__device__ int    g_is64;

// ---------------- JAX threefry2x32 (partitionable scheme) ------------------
struct TF2 { uint32_t a, b; };

__host__ __device__ constexpr uint32_t rotl32(uint32_t v, int r) {
    return (v << r) | (v >> (32 - r));
}

__host__ __device__ constexpr TF2 threefry(uint32_t k0, uint32_t k1,
                                           uint32_t x0, uint32_t x1) {
    const uint32_t ks0 = k0, ks1 = k1, ks2 = k0 ^ k1 ^ 0x1BD11BDAu;
    const int ra[4] = {13, 15, 26, 6};
    const int rb[4] = {17, 29, 16, 24};
    x0 += ks0; x1 += ks1;
#pragma unroll
    for (int i = 0; i < 4; i++) { x0 += x1; x1 = rotl32(x1, ra[i]); x1 ^= x0; }
    x0 += ks1; x1 += ks2 + 1u;
#pragma unroll
    for (int i = 0; i < 4; i++) { x0 += x1; x1 = rotl32(x1, rb[i]); x1 ^= x0; }
    x0 += ks2; x1 += ks0 + 2u;
#pragma unroll
    for (int i = 0; i < 4; i++) { x0 += x1; x1 = rotl32(x1, ra[i]); x1 ^= x0; }
    x0 += ks0; x1 += ks1 + 3u;
#pragma unroll
    for (int i = 0; i < 4; i++) { x0 += x1; x1 = rotl32(x1, rb[i]); x1 ^= x0; }
    x0 += ks1; x1 += ks2 + 4u;
#pragma unroll
    for (int i = 0; i < 4; i++) { x0 += x1; x1 = rotl32(x1, ra[i]); x1 ^= x0; }
    x0 += ks2; x1 += ks0 + 5u;
    return {x0, x1};
}

constexpr TF2 DK0 = threefry(0u, 42u, 0u, 0u);
constexpr TF2 DK1 = threefry(0u, 42u, 0u, 1u);

template <uint32_t K0, uint32_t K1>
__device__ __forceinline__ bool drop_bit(uint32_t j) {
    TF2 r = threefry(K0, K1, 0u, j);
    return ((r.a ^ r.b) >> 31) != 0;   // MSB set -> u >= 0.5 -> dropped
}

// ---------------- packed f32x2 helpers (sm_103a) ---------------------------
typedef unsigned long long ULL;
__device__ __forceinline__ ULL pk2(float x, float y) {
    ULL r;
    asm("mov.b64 %0, {%1, %2};" : "=l"(r) : "f"(x), "f"(y));
    return r;
}
__device__ __forceinline__ ULL fma2(ULL a, ULL b, ULL c) {
    ULL d;
    asm("fma.rn.f32x2 %0, %1, %2, %3;" : "=l"(d) : "l"(a), "l"(b), "l"(c));
    return d;
}
__device__ __forceinline__ void upk2(ULL v, float& x, float& y) {
    asm("mov.b64 {%0, %1}, %2;" : "=f"(x), "=f"(y) : "l"(v));
}

// ---------------- k_pre: dense pre-GEMM + resets + dtype detect -------------
// LDS.128 row loads amortized over 4 k-iterations.
__global__ void __launch_bounds__(256) k_pre(const float* __restrict__ x,
                      const float* __restrict__ Wl,
                      const float* __restrict__ Wr,
                      const uint32_t* __restrict__ ei) {
    __shared__ float2 swlr[64 * 32];      // (Wl, Wr) pairs, 16KB
    __shared__ float  rows[8][4][64];     // 8KB
    int tid = threadIdx.x;
    for (int i = tid; i < 2048; i += 256) swlr[i] = make_float2(Wl[i], Wr[i]);
    int gt = blockIdx.x * 256 + tid;
    if (gt <= N_NODES) g_off[gt] = 0;
    if (blockIdx.x == 0 && tid == 0) {
        int is64 = 1;
        for (int k = 0; k < 64; k++)
            if (ei[2 * k + 1] != 0u) { is64 = 0; break; }
        g_is64 = is64;
    }
    int w = tid >> 5, lane = tid & 31;
    int nb = blockIdx.x * 32 + w * 4;     // grid = 3125 exact
#pragma unroll
    for (int n = 0; n < 4; n++) {
        rows[w][n][lane]      = x[(nb + n) * 64 + lane];
        rows[w][n][32 + lane] = x[(nb + n) * 64 + 32 + lane];
    }
    __syncthreads();
    ULL acc[4];
#pragma unroll
    for (int n = 0; n < 4; n++) acc[n] = pk2(0.f, 0.f);
#pragma unroll
    for (int k4 = 0; k4 < 16; k4++) {
        float4 xv[4];
#pragma unroll
        for (int n = 0; n < 4; n++)
            xv[n] = *reinterpret_cast<const float4*>(&rows[w][n][k4 * 4]);
#pragma unroll
        for (int kk = 0; kk < 4; kk++) {
            float2 wv = swlr[(k4 * 4 + kk) * 32 + lane];
            ULL wp = pk2(wv.x, wv.y);
#pragma unroll
            for (int n = 0; n < 4; n++) {
                float xvv = reinterpret_cast<const float*>(&xv[n])[kk];
                acc[n] = fma2(pk2(xvv, xvv), wp, acc[n]);
            }
        }
    }
#pragma unroll
    for (int n = 0; n < 4; n++) {
        float yl, yr;
        upk2(acc[n], yl, yr);
        g_yh[(nb + n) * 32 + lane] = __float2half_rn(yl);
        g_z[(nb + n) * 32 + lane]  = yr;
    }
}

// ---------------- CSR build (R14 multi-kernel chain, proven fastest) --------
__global__ void k_prep(const uint32_t* __restrict__ ei) {
    int e = blockIdx.x * blockDim.x + threadIdx.x;
    if (e >= N_EDGES) return;
    int s, d;
    if (g_is64) {
        uint2 sv = reinterpret_cast<const uint2*>(ei)[e];
        uint2 dv = reinterpret_cast<const uint2*>(ei)[N_EDGES + e];
        s = (int)sv.x; d = (int)dv.x;
    } else {
        s = (int)ei[e];
        d = (int)ei[N_EDGES + e];
    }
    g_edge[e] = make_int2(s, d);
    atomicAdd(&g_off[d], 1);
}

__global__ void k_scan_a() {
    __shared__ int sh[SCAN_BLK];
    int i = blockIdx.x * SCAN_BLK + threadIdx.x;
    int v = (i < N_NODES) ? g_off[i] : 0;
    sh[threadIdx.x] = v;
    __syncthreads();
    for (int o = 1; o < SCAN_BLK; o <<= 1) {
        int t = (threadIdx.x >= o) ? sh[threadIdx.x - o] : 0;
        __syncthreads();
        sh[threadIdx.x] += t;
        __syncthreads();
    }
    if (i < N_NODES) g_part[i] = sh[threadIdx.x] - v;    // exclusive in-block
    if (threadIdx.x == SCAN_BLK - 1) g_bsum[blockIdx.x] = sh[threadIdx.x];
}

__global__ void k_apply() {
    __shared__ int sh[SCAN_BLK];
    int tid = threadIdx.x, bid = blockIdx.x;
    int v = (tid < NSCAN_BLKS && tid < bid) ? g_bsum[tid] : 0;
    sh[tid] = v;
    __syncthreads();
    for (int o = SCAN_BLK / 2; o > 0; o >>= 1) {
        if (tid < o) sh[tid] += sh[tid + o];
        __syncthreads();
    }
    int base = sh[0];
    int i = bid * SCAN_BLK + tid;
    if (i < N_NODES) {
        int o = g_part[i] + base;
        g_off[i] = o;
        g_cur[i] = o;
    }
    if (bid == 0 && tid == 0) g_off[N_NODES] = N_EDGES;
}

__global__ void k_bucket() {
    int e = blockIdx.x * blockDim.x + threadIdx.x;
    if (e >= N_EDGES) return;
    int2 p = g_edge[e];
    int pos = atomicAdd(&g_cur[p.y], 1);
    g_csr[pos] = p.x;
}

// ---------------- fp16 gather: 4 row-groups x LDG.64 -------------------------
// lane = r*8 + c (r in 0..3 row-group, c in 0..7 uint2 column = 4 halves).
// Returns per-lane float4 partial; after shfl combine, lanes 0..7 hold the
// full sums of columns 4c..4c+3.
__device__ __forceinline__ void acc_u2(float4& ac, uint2 u) {
    float2 a = __half22float2(*reinterpret_cast<const __half2*>(&u.x));
    float2 b = __half22float2(*reinterpret_cast<const __half2*>(&u.y));
    ac.x += a.x; ac.y += a.y; ac.z += b.x; ac.w += b.y;
}

__device__ __forceinline__ float4 gather_u2(const uint2* __restrict__ buf,
                                            int beg, int end, int r, int c) {
    float4 ac = make_float4(0.f, 0.f, 0.f, 0.f);
    int j = beg;
    for (; j + 16 <= end; j += 16) {
        int i0 = __ldg(g_csr + j + r);
        int i1 = __ldg(g_csr + j + 4 + r);
        int i2 = __ldg(g_csr + j + 8 + r);
        int i3 = __ldg(g_csr + j + 12 + r);
        uint2 u0 = __ldg(buf + i0 * 8 + c);
        uint2 u1 = __ldg(buf + i1 * 8 + c);
        uint2 u2 = __ldg(buf + i2 * 8 + c);
        uint2 u3 = __ldg(buf + i3 * 8 + c);
        acc_u2(ac, u0); acc_u2(ac, u1); acc_u2(ac, u2); acc_u2(ac, u3);
    }
    for (; j < end; j += 4) {
        if (j + r < end) {
            int i0 = __ldg(g_csr + j + r);
            uint2 u0 = __ldg(buf + i0 * 8 + c);
            acc_u2(ac, u0);
        }
    }
    // combine the 4 row-groups (xor 8, 16)
#pragma unroll
    for (int o = 8; o <= 16; o <<= 1) {
        ac.x += __shfl_xor_sync(0xffffffffu, ac.x, o);
        ac.y += __shfl_xor_sync(0xffffffffu, ac.y, o);
        ac.z += __shfl_xor_sync(0xffffffffu, ac.z, o);
        ac.w += __shfl_xor_sync(0xffffffffu, ac.w, o);
    }
    return ac;
}

// layer 1: warp per node; gather-mean + bias + z + lrelu + dropout (1 hash)
__global__ void k_agg1(const float* __restrict__ b) {
    int w = threadIdx.x >> 5, lane = threadIdx.x & 31;
    int r = lane >> 3, c = lane & 7;
    int node = blockIdx.x * 8 + w;                    // grid = 12500 exact
    int beg = g_off[node], end = g_off[node + 1];
    float4 acc = gather_u2(reinterpret_cast<const uint2*>(g_yh), beg, end, r, c);
    // one lane-parallel threefry covers all 32 elements of this node
    uint32_t m = __ballot_sync(0xffffffffu,
                 drop_bit<DK0.a, DK0.b>((uint32_t)(node * 32) + (uint32_t)lane));
    if (lane < 8) {
        int c4 = 4 * lane;
        float inv = 1.0f / fmaxf((float)(end - beg), 1.0f);
        float4 z4 = *reinterpret_cast<const float4*>(g_z + node * 32 + c4);
        float4 b4 = *reinterpret_cast<const float4*>(b + c4);
        float v0 = fmaf(acc.x, inv, b4.x + z4.x);
        float v1 = fmaf(acc.y, inv, b4.y + z4.y);
        float v2 = fmaf(acc.z, inv, b4.z + z4.z);
        float v3 = fmaf(acc.w, inv, b4.w + z4.w);
        v0 = v0 > 0.f ? v0 : 0.01f * v0;
        v1 = v1 > 0.f ? v1 : 0.01f * v1;
        v2 = v2 > 0.f ? v2 : 0.01f * v2;
        v3 = v3 > 0.f ? v3 : 0.01f * v3;
        v0 = ((m >> (c4 + 0)) & 1u) ? 0.f : 2.0f * v0;
        v1 = ((m >> (c4 + 1)) & 1u) ? 0.f : 2.0f * v1;
        v2 = ((m >> (c4 + 2)) & 1u) ? 0.f : 2.0f * v2;
        v3 = ((m >> (c4 + 3)) & 1u) ? 0.f : 2.0f * v3;
        *reinterpret_cast<float4*>(g_h1f + node * 32 + c4) =
            make_float4(v0, v1, v2, v3);
        __half2 lo = __floats2half2_rn(v0, v1);
        __half2 hi = __floats2half2_rn(v2, v3);
        uint2 pk;
        pk.x = *reinterpret_cast<uint32_t*>(&lo);
        pk.y = *reinterpret_cast<uint32_t*>(&hi);
        reinterpret_cast<uint2*>(g_h1h)[node * 8 + lane] = pk;
    }
}

// layer 2 gather: warp per node; gather-mean of h1 -> g_m2 (fp32)
__global__ void k_gather2() {
    int w = threadIdx.x >> 5, lane = threadIdx.x & 31;
    int r = lane >> 3, c = lane & 7;
    int node = blockIdx.x * 8 + w;                    // grid = 12500 exact
    int beg = g_off[node], end = g_off[node + 1];
    float4 acc = gather_u2(reinterpret_cast<const uint2*>(g_h1h), beg, end, r, c);
    if (lane < 8) {
        float inv = 1.0f / fmaxf((float)(end - beg), 1.0f);
        *reinterpret_cast<float4*>(g_m2 + node * 32 + 4 * lane) =
            make_float4(acc.x * inv, acc.y * inv, acc.z * inv, acc.w * inv);
    }
}

// layer 2 dense: GEMMs (4 nodes/warp, LDS.128 row loads) + dropout + l2norm
__global__ void __launch_bounds__(256) k_gemm2(const float* __restrict__ Wl,
                       const float* __restrict__ b,
                       const float* __restrict__ Wr,
                       float* __restrict__ out) {
    __shared__ float2 swl2[32 * 32], swr2[32 * 32];   // 8KB + 8KB
    __shared__ float  rows[8][4][64];                 // 8KB
    int tid = threadIdx.x;
    for (int i = tid; i < 1024; i += 256) {
        int k = i >> 5, c = i & 31;
        swl2[i] = make_float2(Wl[k * 64 + c], Wl[k * 64 + 32 + c]);
        swr2[i] = make_float2(Wr[k * 64 + c], Wr[k * 64 + 32 + c]);
    }
    __syncthreads();
    int w = tid >> 5, lane = tid & 31;
    int nb = blockIdx.x * 32 + w * 4;                 // grid = 3125 exact
#pragma unroll
    for (int n = 0; n < 4; n++) {
        int node = nb + n;
        rows[w][n][lane]      = g_m2[node * 32 + lane];
        rows[w][n][32 + lane] = g_h1f[node * 32 + lane];
    }
    __syncwarp();
    float bb0 = b[lane], bb1 = b[32 + lane];
    float a0[4], a1[4];
#pragma unroll
    for (int n = 0; n < 4; n++) { a0[n] = bb0; a1[n] = bb1; }
#pragma unroll
    for (int k4 = 0; k4 < 8; k4++) {
        float4 m4[4], h4[4];
#pragma unroll
        for (int n = 0; n < 4; n++) {
            m4[n] = *reinterpret_cast<const float4*>(&rows[w][n][k4 * 4]);
            h4[n] = *reinterpret_cast<const float4*>(&rows[w][n][32 + k4 * 4]);
        }
#pragma unroll
        for (int kk = 0; kk < 4; kk++) {
            float2 wl = swl2[(k4 * 4 + kk) * 32 + lane];
            float2 wr = swr2[(k4 * 4 + kk) * 32 + lane];
#pragma unroll
            for (int n = 0; n < 4; n++) {
                float m = reinterpret_cast<const float*>(&m4[n])[kk];
                float h = reinterpret_cast<const float*>(&h4[n])[kk];
                a0[n] = fmaf(m, wl.x, fmaf(h, wr.x, a0[n]));
                a1[n] = fmaf(m, wl.y, fmaf(h, wr.y, a1[n]));
            }
        }
    }
#pragma unroll
    for (int n = 0; n < 4; n++) {
        int node = nb + n;
        uint32_t j0 = (uint32_t)(node * 64 + lane);
        float v0 = drop_bit<DK1.a, DK1.b>(j0)       ? 0.f : 2.0f * a0[n];
        float v1 = drop_bit<DK1.a, DK1.b>(j0 + 32u) ? 0.f : 2.0f * a1[n];
        float ss = v0 * v0 + v1 * v1;
#pragma unroll
        for (int o = 16; o > 0; o >>= 1)
            ss += __shfl_xor_sync(0xffffffffu, ss, o);
        float scale = 1.0f / fmaxf(sqrtf(ss), 1e-12f);
        out[node * 64 + lane]      = v0 * scale;
        out[node * 64 + 32 + lane] = v1 * scale;
    }
}

// ---------------- launch -----------------------------------------------------
extern "C" void kernel_launch(void* const* d_in, const int* in_sizes, int n_in,
                              void* d_out, int out_size) {
    const float*    x   = (const float*)d_in[0];
    const uint32_t* ei  = (const uint32_t*)d_in[1];   // int32 or int64 (detected)
    const float*    W1l = (const float*)d_in[2];
    const float*    b1  = (const float*)d_in[3];
    const float*    W1r = (const float*)d_in[4];
    const float*    W2l = (const float*)d_in[5];
    const float*    b2  = (const float*)d_in[6];
    const float*    W2r = (const float*)d_in[7];
    float* out = (float*)d_out;

    k_pre<<<N_NODES / 32, 256>>>(x, W1l, W1r, ei);     // 3125 blocks
    k_prep<<<(N_EDGES + 255) / 256, 256>>>(ei);        // 6250 blocks
    k_scan_a<<<NSCAN_BLKS, SCAN_BLK>>>();
    k_apply<<<NSCAN_BLKS, SCAN_BLK>>>();
    k_bucket<<<(N_EDGES + 255) / 256, 256>>>();        // 6250 blocks
    k_agg1<<<N_NODES / 8, 256>>>(b1);                  // 12500 blocks
    k_gather2<<<N_NODES / 8, 256>>>();                 // 12500 blocks
    k_gemm2<<<N_NODES / 32, 256>>>(W2l, b2, W2r, out); // 3125 blocks
}

// round 17
// speedup vs baseline: 1.0948x; 1.0046x over previous
#include <cuda_runtime.h>
#include <cuda_fp16.h>
#include <cstdint>

#define N_NODES 100000
#define N_EDGES 1600000
#define SCAN_BLK 512
#define NSCAN_BLKS 196   // 196*512 >= N_NODES

// ---------------- scratch (device globals; no allocation allowed) ----------
__device__ __half g_yh[N_NODES * 32];   // x @ W1_l  (fp16, gather source)
__device__ float  g_z[N_NODES * 32];    // x @ W1_r  (fp32)
__device__ __half g_h1h[N_NODES * 32];  // h1 fp16 (gather source, layer 2)
__device__ float  g_h1f[N_NODES * 32];  // h1 fp32 (dense self term)
__device__ float  g_m2[N_NODES * 32];   // layer-2 gathered mean
__device__ int2   g_edge[N_EDGES];      // packed (src, dst)
__device__ int    g_csr[N_EDGES];       // src ids grouped by dst
__device__ int    g_off[N_NODES + 1];   // counts -> exclusive offsets
__device__ int    g_cur[N_NODES];       // bucket cursors
__device__ int    g_bsum[256];
__device__ int    g_sflag[NSCAN_BLKS];
__device__ int    g_is64;

// ---------------- JAX threefry2x32 (partitionable scheme) ------------------
struct TF2 { uint32_t a, b; };

__host__ __device__ constexpr uint32_t rotl32(uint32_t v, int r) {
    return (v << r) | (v >> (32 - r));
}

__host__ __device__ constexpr TF2 threefry(uint32_t k0, uint32_t k1,
                                           uint32_t x0, uint32_t x1) {
    const uint32_t ks0 = k0, ks1 = k1, ks2 = k0 ^ k1 ^ 0x1BD11BDAu;
    const int ra[4] = {13, 15, 26, 6};
    const int rb[4] = {17, 29, 16, 24};
    x0 += ks0; x1 += ks1;
#pragma unroll
    for (int i = 0; i < 4; i++) { x0 += x1; x1 = rotl32(x1, ra[i]); x1 ^= x0; }
    x0 += ks1; x1 += ks2 + 1u;
#pragma unroll
    for (int i = 0; i < 4; i++) { x0 += x1; x1 = rotl32(x1, rb[i]); x1 ^= x0; }
    x0 += ks2; x1 += ks0 + 2u;
#pragma unroll
    for (int i = 0; i < 4; i++) { x0 += x1; x1 = rotl32(x1, ra[i]); x1 ^= x0; }
    x0 += ks0; x1 += ks1 + 3u;
#pragma unroll
    for (int i = 0; i < 4; i++) { x0 += x1; x1 = rotl32(x1, rb[i]); x1 ^= x0; }
    x0 += ks1; x1 += ks2 + 4u;
#pragma unroll
    for (int i = 0; i < 4; i++) { x0 += x1; x1 = rotl32(x1, ra[i]); x1 ^= x0; }
    x0 += ks2; x1 += ks0 + 5u;
    return {x0, x1};
}

constexpr TF2 DK0 = threefry(0u, 42u, 0u, 0u);
constexpr TF2 DK1 = threefry(0u, 42u, 0u, 1u);

template <uint32_t K0, uint32_t K1>
__device__ __forceinline__ bool drop_bit(uint32_t j) {
    TF2 r = threefry(K0, K1, 0u, j);
    return ((r.a ^ r.b) >> 31) != 0;   // MSB set -> u >= 0.5 -> dropped
}

// ---------------- packed f32x2 helpers (sm_103a) ---------------------------
typedef unsigned long long ULL;
__device__ __forceinline__ ULL pk2(float x, float y) {
    ULL r;
    asm("mov.b64 %0, {%1, %2};" : "=l"(r) : "f"(x), "f"(y));
    return r;
}
__device__ __forceinline__ ULL fma2(ULL a, ULL b, ULL c) {
    ULL d;
    asm("fma.rn.f32x2 %0, %1, %2, %3;" : "=l"(d) : "l"(a), "l"(b), "l"(c));
    return d;
}
__device__ __forceinline__ void upk2(ULL v, float& x, float& y) {
    asm("mov.b64 {%0, %1}, %2;" : "=f"(x), "=f"(y) : "l"(v));
}

// ---------------- k_pre: dense pre-GEMM + resets + dtype detect -------------
__global__ void __launch_bounds__(256) k_pre(const float* __restrict__ x,
                      const float* __restrict__ Wl,
                      const float* __restrict__ Wr,
                      const uint32_t* __restrict__ ei) {
    __shared__ float2 swlr[64 * 32];      // (Wl, Wr) pairs, 16KB
    __shared__ float  rows[8][4][64];     // 8KB
    int tid = threadIdx.x;
    for (int i = tid; i < 2048; i += 256) swlr[i] = make_float2(Wl[i], Wr[i]);
    int gt = blockIdx.x * 256 + tid;
    if (gt <= N_NODES) g_off[gt] = 0;
    if (gt < NSCAN_BLKS) g_sflag[gt] = 0;
    if (blockIdx.x == 0 && tid == 0) {
        int is64 = 1;
        for (int k = 0; k < 64; k++)
            if (ei[2 * k + 1] != 0u) { is64 = 0; break; }
        g_is64 = is64;
    }
    int w = tid >> 5, lane = tid & 31;
    int nb = blockIdx.x * 32 + w * 4;     // grid = 3125 exact
#pragma unroll
    for (int n = 0; n < 4; n++) {
        rows[w][n][lane]      = x[(nb + n) * 64 + lane];
        rows[w][n][32 + lane] = x[(nb + n) * 64 + 32 + lane];
    }
    __syncthreads();
    ULL acc[4];
#pragma unroll
    for (int n = 0; n < 4; n++) acc[n] = pk2(0.f, 0.f);
#pragma unroll
    for (int k4 = 0; k4 < 16; k4++) {
        float4 xv[4];
#pragma unroll
        for (int n = 0; n < 4; n++)
            xv[n] = *reinterpret_cast<const float4*>(&rows[w][n][k4 * 4]);
#pragma unroll
        for (int kk = 0; kk < 4; kk++) {
            float2 wv = swlr[(k4 * 4 + kk) * 32 + lane];
            ULL wp = pk2(wv.x, wv.y);
#pragma unroll
            for (int n = 0; n < 4; n++) {
                float xvv = reinterpret_cast<const float*>(&xv[n])[kk];
                acc[n] = fma2(pk2(xvv, xvv), wp, acc[n]);
            }
        }
    }
#pragma unroll
    for (int n = 0; n < 4; n++) {
        float yl, yr;
        upk2(acc[n], yl, yr);
        g_yh[(nb + n) * 32 + lane] = __float2half_rn(yl);
        g_z[(nb + n) * 32 + lane]  = yr;
    }
}

// ---------------- CSR build --------------------------------------------------
// prep: 2 edges per thread, vector loads
__global__ void k_prep(const uint32_t* __restrict__ ei) {
    int e2 = (blockIdx.x * blockDim.x + threadIdx.x) * 2;  // grid covers E/2
    if (e2 >= N_EDGES) return;
    int s0, d0, s1, d1;
    if (g_is64) {
        uint4 sp = __ldg(reinterpret_cast<const uint4*>(ei) + (e2 >> 1));
        uint4 dp = __ldg(reinterpret_cast<const uint4*>(ei) + ((N_EDGES + e2) >> 1));
        s0 = (int)sp.x; s1 = (int)sp.z;
        d0 = (int)dp.x; d1 = (int)dp.z;
    } else {
        uint2 sp = __ldg(reinterpret_cast<const uint2*>(ei) + (e2 >> 1));
        uint2 dp = __ldg(reinterpret_cast<const uint2*>(ei) + ((N_EDGES + e2) >> 1));
        s0 = (int)sp.x; s1 = (int)sp.y;
        d0 = (int)dp.x; d1 = (int)dp.y;
    }
    *reinterpret_cast<int4*>(g_edge + e2) = make_int4(s0, d0, s1, d1);
    atomicAdd(&g_off[d0], 1);
    atomicAdd(&g_off[d1], 1);
}

// fused scan: per-chunk scan + flag-wait + base reduce + write offsets.
// All 196 blocks co-resident (512thr/2KB/16regs) -> spin is deadlock-free.
__global__ void k_scan() {
    __shared__ int sh[SCAN_BLK];
    int tid = threadIdx.x, bid = blockIdx.x;
    int i = bid * SCAN_BLK + tid;
    int v = (i < N_NODES) ? g_off[i] : 0;
    sh[tid] = v;
    __syncthreads();
    for (int o = 1; o < SCAN_BLK; o <<= 1) {
        int t = (tid >= o) ? sh[tid - o] : 0;
        __syncthreads();
        sh[tid] += t;
        __syncthreads();
    }
    int ex = sh[tid] - v;          // exclusive in-chunk
    if (tid == 0) {
        g_bsum[bid] = sh[SCAN_BLK - 1];
        __threadfence();
        atomicExch(&g_sflag[bid], 1);
    }
    // wait for all preceding chunks' totals
    if (tid < bid) {
        while (atomicAdd(&g_sflag[tid], 0) == 0) __nanosleep(32);
    }
    __syncthreads();
    int pv = (tid < bid) ? __ldcg(&g_bsum[tid]) : 0;   // bid <= 195 < 512
    sh[tid] = pv;
    __syncthreads();
    for (int o = SCAN_BLK / 2; o > 0; o >>= 1) {
        if (tid < o) sh[tid] += sh[tid + o];
        __syncthreads();
    }
    int base = sh[0];
    if (i < N_NODES) {
        int o = ex + base;
        g_off[i] = o;
        g_cur[i] = o;
    }
    if (i == 0) g_off[N_NODES] = N_EDGES;
}

// bucket: 2 edges per thread
__global__ void k_bucket() {
    int t = blockIdx.x * blockDim.x + threadIdx.x;     // covers E/2
    if (t * 2 >= N_EDGES) return;
    int4 p = __ldg(reinterpret_cast<const int4*>(g_edge) + t);
    int pos0 = atomicAdd(&g_cur[p.y], 1);
    g_csr[pos0] = p.x;
    int pos1 = atomicAdd(&g_cur[p.w], 1);
    g_csr[pos1] = p.z;
}

// ---------------- fp16 gather: 4 row-groups x LDG.64, fp16 pair-add ---------
__device__ __forceinline__ void acc_u2(float4& ac, uint2 u) {
    float2 a = __half22float2(*reinterpret_cast<const __half2*>(&u.x));
    float2 b = __half22float2(*reinterpret_cast<const __half2*>(&u.y));
    ac.x += a.x; ac.y += a.y; ac.z += b.x; ac.w += b.y;
}

__device__ __forceinline__ float4 gather_u2(const uint2* __restrict__ buf,
                                            int beg, int end, int r, int c) {
    float4 ac = make_float4(0.f, 0.f, 0.f, 0.f);
    int j = beg;
    for (; j + 16 <= end; j += 16) {
        int i0 = __ldg(g_csr + j + r);
        int i1 = __ldg(g_csr + j + 4 + r);
        int i2 = __ldg(g_csr + j + 8 + r);
        int i3 = __ldg(g_csr + j + 12 + r);
        uint2 u0 = __ldg(buf + i0 * 8 + c);
        uint2 u1 = __ldg(buf + i1 * 8 + c);
        uint2 u2 = __ldg(buf + i2 * 8 + c);
        uint2 u3 = __ldg(buf + i3 * 8 + c);
        // one-level fp16 pairing (u0+u1, u2+u3), then fp32 accumulate
        __half2 p0 = __hadd2(*reinterpret_cast<const __half2*>(&u0.x),
                             *reinterpret_cast<const __half2*>(&u1.x));
        __half2 p1 = __hadd2(*reinterpret_cast<const __half2*>(&u0.y),
                             *reinterpret_cast<const __half2*>(&u1.y));
        __half2 p2 = __hadd2(*reinterpret_cast<const __half2*>(&u2.x),
                             *reinterpret_cast<const __half2*>(&u3.x));
        __half2 p3 = __hadd2(*reinterpret_cast<const __half2*>(&u2.y),
                             *reinterpret_cast<const __half2*>(&u3.y));
        float2 f0 = __half22float2(p0);
        float2 f1 = __half22float2(p1);
        float2 f2 = __half22float2(p2);
        float2 f3 = __half22float2(p3);
        ac.x += f0.x + f2.x;
        ac.y += f0.y + f2.y;
        ac.z += f1.x + f3.x;
        ac.w += f1.y + f3.y;
    }
    for (; j < end; j += 4) {
        if (j + r < end) {
            int i0 = __ldg(g_csr + j + r);
            uint2 u0 = __ldg(buf + i0 * 8 + c);
            acc_u2(ac, u0);
        }
    }
    // combine the 4 row-groups (xor 8, 16)
#pragma unroll
    for (int o = 8; o <= 16; o <<= 1) {
        ac.x += __shfl_xor_sync(0xffffffffu, ac.x, o);
        ac.y += __shfl_xor_sync(0xffffffffu, ac.y, o);
        ac.z += __shfl_xor_sync(0xffffffffu, ac.z, o);
        ac.w += __shfl_xor_sync(0xffffffffu, ac.w, o);
    }
    return ac;
}

// layer 1: warp per node; gather-mean + bias + z + lrelu + dropout (1 hash)
__global__ void k_agg1(const float* __restrict__ b) {
    int w = threadIdx.x >> 5, lane = threadIdx.x & 31;
    int r = lane >> 3, c = lane & 7;
    int node = blockIdx.x * 8 + w;                    // grid = 12500 exact
    int beg = g_off[node], end = g_off[node + 1];
    float4 acc = gather_u2(reinterpret_cast<const uint2*>(g_yh), beg, end, r, c);
    uint32_t m = __ballot_sync(0xffffffffu,
                 drop_bit<DK0.a, DK0.b>((uint32_t)(node * 32) + (uint32_t)lane));
    if (lane < 8) {
        int c4 = 4 * lane;
        float inv = 1.0f / fmaxf((float)(end - beg), 1.0f);
        float4 z4 = *reinterpret_cast<const float4*>(g_z + node * 32 + c4);
        float4 b4 = *reinterpret_cast<const float4*>(b + c4);
        float v0 = fmaf(acc.x, inv, b4.x + z4.x);
        float v1 = fmaf(acc.y, inv, b4.y + z4.y);
        float v2 = fmaf(acc.z, inv, b4.z + z4.z);
        float v3 = fmaf(acc.w, inv, b4.w + z4.w);
        v0 = v0 > 0.f ? v0 : 0.01f * v0;
        v1 = v1 > 0.f ? v1 : 0.01f * v1;
        v2 = v2 > 0.f ? v2 : 0.01f * v2;
        v3 = v3 > 0.f ? v3 : 0.01f * v3;
        v0 = ((m >> (c4 + 0)) & 1u) ? 0.f : 2.0f * v0;
        v1 = ((m >> (c4 + 1)) & 1u) ? 0.f : 2.0f * v1;
        v2 = ((m >> (c4 + 2)) & 1u) ? 0.f : 2.0f * v2;
        v3 = ((m >> (c4 + 3)) & 1u) ? 0.f : 2.0f * v3;
        *reinterpret_cast<float4*>(g_h1f + node * 32 + c4) =
            make_float4(v0, v1, v2, v3);
        __half2 lo = __floats2half2_rn(v0, v1);
        __half2 hi = __floats2half2_rn(v2, v3);
        uint2 pk;
        pk.x = *reinterpret_cast<uint32_t*>(&lo);
        pk.y = *reinterpret_cast<uint32_t*>(&hi);
        reinterpret_cast<uint2*>(g_h1h)[node * 8 + lane] = pk;
    }
}

// layer 2 gather: warp per node; gather-mean of h1 -> g_m2 (fp32)
__global__ void k_gather2() {
    int w = threadIdx.x >> 5, lane = threadIdx.x & 31;
    int r = lane >> 3, c = lane & 7;
    int node = blockIdx.x * 8 + w;                    // grid = 12500 exact
    int beg = g_off[node], end = g_off[node + 1];
    float4 acc = gather_u2(reinterpret_cast<const uint2*>(g_h1h), beg, end, r, c);
    if (lane < 8) {
        float inv = 1.0f / fmaxf((float)(end - beg), 1.0f);
        *reinterpret_cast<float4*>(g_m2 + node * 32 + 4 * lane) =
            make_float4(acc.x * inv, acc.y * inv, acc.z * inv, acc.w * inv);
    }
}

// layer 2 dense: GEMMs (4 nodes/warp, LDS.128 row loads) + dropout + l2norm
__global__ void __launch_bounds__(256) k_gemm2(const float* __restrict__ Wl,
                       const float* __restrict__ b,
                       const float* __restrict__ Wr,
                       float* __restrict__ out) {
    __shared__ float2 swl2[32 * 32], swr2[32 * 32];   // 8KB + 8KB
    __shared__ float  rows[8][4][64];                 // 8KB
    int tid = threadIdx.x;
    for (int i = tid; i < 1024; i += 256) {
        int k = i >> 5, c = i & 31;
        swl2[i] = make_float2(Wl[k * 64 + c], Wl[k * 64 + 32 + c]);
        swr2[i] = make_float2(Wr[k * 64 + c], Wr[k * 64 + 32 + c]);
    }
    __syncthreads();
    int w = tid >> 5, lane = tid & 31;
    int nb = blockIdx.x * 32 + w * 4;                 // grid = 3125 exact
#pragma unroll
    for (int n = 0; n < 4; n++) {
        int node = nb + n;
        rows[w][n][lane]      = g_m2[node * 32 + lane];
        rows[w][n][32 + lane] = g_h1f[node * 32 + lane];
    }
    __syncwarp();
    float bb0 = b[lane], bb1 = b[32 + lane];
    float a0[4], a1[4];
#pragma unroll
    for (int n = 0; n < 4; n++) { a0[n] = bb0; a1[n] = bb1; }
#pragma unroll
    for (int k4 = 0; k4 < 8; k4++) {
        float4 m4[4], h4[4];
#pragma unroll
        for (int n = 0; n < 4; n++) {
            m4[n] = *reinterpret_cast<const float4*>(&rows[w][n][k4 * 4]);
            h4[n] = *reinterpret_cast<const float4*>(&rows[w][n][32 + k4 * 4]);
        }
#pragma unroll
        for (int kk = 0; kk < 4; kk++) {
            float2 wl = swl2[(k4 * 4 + kk) * 32 + lane];
            float2 wr = swr2[(k4 * 4 + kk) * 32 + lane];
#pragma unroll
            for (int n = 0; n < 4; n++) {
                float m = reinterpret_cast<const float*>(&m4[n])[kk];
                float h = reinterpret_cast<const float*>(&h4[n])[kk];
                a0[n] = fmaf(m, wl.x, fmaf(h, wr.x, a0[n]));
                a1[n] = fmaf(m, wl.y, fmaf(h, wr.y, a1[n]));
            }
        }
    }
#pragma unroll
    for (int n = 0; n < 4; n++) {
        int node = nb + n;
        uint32_t j0 = (uint32_t)(node * 64 + lane);
        float v0 = drop_bit<DK1.a, DK1.b>(j0)       ? 0.f : 2.0f * a0[n];
        float v1 = drop_bit<DK1.a, DK1.b>(j0 + 32u) ? 0.f : 2.0f * a1[n];
        float ss = v0 * v0 + v1 * v1;
#pragma unroll
        for (int o = 16; o > 0; o >>= 1)
            ss += __shfl_xor_sync(0xffffffffu, ss, o);
        float scale = 1.0f / fmaxf(sqrtf(ss), 1e-12f);
        out[node * 64 + lane]      = v0 * scale;
        out[node * 64 + 32 + lane] = v1 * scale;
    }
}

// ---------------- launch -----------------------------------------------------
extern "C" void kernel_launch(void* const* d_in, const int* in_sizes, int n_in,
                              void* d_out, int out_size) {
    const float*    x   = (const float*)d_in[0];
    const uint32_t* ei  = (const uint32_t*)d_in[1];   // int32 or int64 (detected)
    const float*    W1l = (const float*)d_in[2];
    const float*    b1  = (const float*)d_in[3];
    const float*    W1r = (const float*)d_in[4];
    const float*    W2l = (const float*)d_in[5];
    const float*    b2  = (const float*)d_in[6];
    const float*    W2r = (const float*)d_in[7];
    float* out = (float*)d_out;

    k_pre<<<N_NODES / 32, 256>>>(x, W1l, W1r, ei);        // 3125 blocks
    k_prep<<<(N_EDGES / 2 + 255) / 256, 256>>>(ei);       // 3125 blocks
    k_scan<<<NSCAN_BLKS, SCAN_BLK>>>();                   // fused scan+apply
    k_bucket<<<(N_EDGES / 2 + 255) / 256, 256>>>();       // 3125 blocks
    k_agg1<<<N_NODES / 8, 256>>>(b1);                     // 12500 blocks
    k_gather2<<<N_NODES / 8, 256>>>();                    // 12500 blocks
    k_gemm2<<<N_NODES / 32, 256>>>(W2l, b2, W2r, out);    // 3125 blocks
}